// round 13
// baseline (speedup 1.0000x reference)
#include <cuda_runtime.h>
#include <cuda_fp16.h>
#include <cstdint>
#include <cstddef>

// Problem constants
#define B_  2
#define S_  400
#define D_  512
#define ROWS (B_ * S_)                  // 800
#define ALIGN_OFF (S_ * B_ * D_)        // 409600

// Scratch (device globals: no allocation allowed)
__device__ __half g_wq_h[ROWS * D_];
__device__ __half g_uh_h[ROWS * D_];
__device__ __half g_in_h[ROWS * D_];
__device__ __half g_mem_h[ROWS * D_];
__device__ __half g_memT_h[B_ * D_ * S_];      // per b: [512][400]
__device__ __half g_WqT[D_ * D_];              // [n][k]
__device__ __half g_WcT[D_ * D_];
__device__ __half g_WoutT[D_ * 2 * D_];        // [512][1024]
__device__ __half g_ctx_h[ROWS * D_];
__device__ __half g_align_h[S_ * B_ * S_];     // [t][b][s]

// ---------------------------------------------------------------------------
__device__ __forceinline__ __half2 tanh2_fast(__half2 x) {
    uint32_t xi = *(uint32_t*)&x, yi;
    asm("tanh.approx.f16x2 %0, %1;" : "=r"(yi) : "r"(xi));
    return *(__half2*)&yi;
}

__device__ __forceinline__ uint32_t smem_u32(const void* p) {
    uint32_t a;
    asm("{ .reg .u64 t; cvta.to.shared.u64 t, %1; cvt.u32.u64 %0, t; }"
        : "=r"(a) : "l"(p));
    return a;
}

#define MBAR_INIT(mbar, cnt) \
    asm volatile("mbarrier.init.shared.b64 [%0], %1;" \
        :: "r"((uint32_t)(mbar)), "r"((uint32_t)(cnt)) : "memory")

#define MBAR_WAIT(mbar, parity) do { \
    uint32_t _m = (uint32_t)(mbar); uint32_t _p = (uint32_t)(parity); uint32_t _d; \
    asm volatile("{\n\t.reg .pred p;\n\t" \
        "mbarrier.try_wait.parity.acquire.cta.shared::cta.b64 p, [%1], %2;\n\t" \
        "selp.b32 %0, 1, 0, p;\n\t}" : "=r"(_d) : "r"(_m), "r"(_p) : "memory"); \
    if (!_d) { \
        asm volatile("{\n\t.reg .pred P1;\n\t" \
            "WL_%=:\n\t" \
            "mbarrier.try_wait.parity.acquire.cta.shared::cta.b64 P1, [%0], %1, 0x989680;\n\t" \
            "@P1 bra.uni WD_%=;\n\t" \
            "bra.uni WL_%=;\n\t" \
            "WD_%=:\n\t}" :: "r"(_m), "r"(_p) : "memory"); \
    } \
} while (0)

__device__ __forceinline__ void bulk_cp(uint32_t dst, const void* src,
                                        uint32_t bytes, uint32_t mbar) {
    asm volatile(
        "cp.async.bulk.shared::cluster.global.mbarrier::complete_tx::bytes "
        "[%0], [%1], %2, [%3];"
        :: "r"(dst), "l"(src), "r"(bytes), "r"(mbar) : "memory");
}

__device__ __forceinline__ void ldsm_x4(uint32_t* r, uint32_t addr) {
    asm volatile("ldmatrix.sync.aligned.m8n8.x4.shared.b16 {%0,%1,%2,%3}, [%4];"
                 : "=r"(r[0]), "=r"(r[1]), "=r"(r[2]), "=r"(r[3]) : "r"(addr));
}

__device__ __forceinline__ void mma16(float* d, const uint32_t* a,
                                      uint32_t b0, uint32_t b1) {
    asm volatile(
        "mma.sync.aligned.m16n8k16.row.col.f32.f16.f16.f32 "
        "{%0,%1,%2,%3}, {%4,%5,%6,%7}, {%8,%9}, {%0,%1,%2,%3};"
        : "+f"(d[0]), "+f"(d[1]), "+f"(d[2]), "+f"(d[3])
        : "r"(a[0]), "r"(a[1]), "r"(a[2]), "r"(a[3]), "r"(b0), "r"(b1));
}

struct GemmArgs {
    const __half* A;      // [M, KA] row-major, lda (halves)
    const __half* A2;     // [M, K-KA] row-major, lda (concat tail)
    const __half* Bt;     // [N, K] row-major, ldb  (B transposed)
    const float*  bias;   // [N] or null
    float*        C;      // f32 out (omode 0/1)
    __half*       Ch;     // f16 out (omode 2)
};

// ---------------------------------------------------------------------------
// fp16 mma.sync GEMM, 64x64 CTA tile, 256 threads (8 warps: 2M x 4N).
// K staged by KS via cp.async.bulk; 4 buffers, prefetch distance 3,
// one mbarrier per buffer. ldmatrix.x4 fragments.
// omode 0: C[r*ldc+c] f32; 1: [T,B,D] scatter f32; 2: Ch[r*ldc+c] f16.
// Requires KS%16==0, KA%KS==0 (or KA>=K). smem = 4*2*64*(KS+8)*2 bytes.
// ---------------------------------------------------------------------------
__global__ void __launch_bounds__(256, 1) gemm_f16(
    GemmArgs ga0, GemmArgs ga1, int lda, int KA, int ldb, int ldc,
    int omode, int M, int K, int KS)
{
    extern __shared__ __half sh[];
    __shared__ uint64_t mbars[4];

    const GemmArgs g = blockIdx.z ? ga1 : ga0;
    const int tid = threadIdx.x, warp = tid >> 5, lane = tid & 31;
    const int q = lane >> 2, r = lane & 3;
    const int wm = warp >> 2;                  // 0..1 : M offset 32*wm
    const int wn = warp & 3;                   // 0..3 : N offset 16*wn
    const int row0 = blockIdx.y * 64;
    const int col0 = blockIdx.x * 64;
    const int RS = KS + 8;                     // halves per smem row
    const int ns = K / KS;
    const uint32_t shb = smem_u32(sh);
    const uint32_t mb  = smem_u32(mbars);
    const uint32_t boff = 4u * 64u * (uint32_t)RS;   // halves (B region offset)

    if (tid < 4) MBAR_INIT(mb + tid * 8, 1);
    __syncthreads();

    const int  lrow  = tid & 63;
    const bool isA   = tid < 64;
    const bool isLd  = tid < 128;
    const int  arow_g = row0 + lrow;
    const int  arow_c = (arow_g < M) ? arow_g : (M - 1);
    const uint32_t stage_bytes = (uint32_t)KS * 2u * 128u;

    auto issue = [&](int c) {
        const int bi = c & 3;
        const uint32_t mbar = mb + (uint32_t)bi * 8u;
        if (tid == 0)
            asm volatile("mbarrier.arrive.expect_tx.shared.b64 _, [%0], %1;"
                         :: "r"(mbar), "r"(stage_bytes) : "memory");
        if (isLd) {
            const int k0 = c * KS;
            const __half* src;
            uint32_t dst;
            if (isA) {
                const __half* Ab = (k0 < KA) ? g.A : g.A2;
                const int kk = (k0 < KA) ? k0 : (k0 - KA);
                src = Ab + (size_t)arow_c * lda + kk;
                dst = shb + (uint32_t)((bi * 64 + lrow) * RS) * 2u;
            } else {
                src = g.Bt + (size_t)(col0 + lrow) * ldb + (size_t)c * KS;
                dst = shb + (boff + (uint32_t)((bi * 64 + lrow) * RS)) * 2u;
            }
            bulk_cp(dst, src, (uint32_t)KS * 2u, mbar);
        }
    };

    float acc[2][2][4];
    #pragma unroll
    for (int i = 0; i < 2; ++i)
        #pragma unroll
        for (int j2 = 0; j2 < 2; ++j2)
            #pragma unroll
            for (int k2 = 0; k2 < 4; ++k2) acc[i][j2][k2] = 0.f;

    // prologue: up to 3 stages in flight
    if (ns > 0) issue(0);
    if (ns > 1) issue(1);
    if (ns > 2) issue(2);

    int p0 = 0, p1 = 0, p2 = 0, p3 = 0;

    const int j   = lane & 7;
    const int sm8 = (lane >> 3) & 1;
    const int sk8 = (lane >> 4) & 1;

    for (int c = 0; c < ns; ++c) {
        const int bi = c & 3;
        switch (bi) {
            case 0: MBAR_WAIT(mb,      p0); p0 ^= 1; break;
            case 1: MBAR_WAIT(mb + 8,  p1); p1 ^= 1; break;
            case 2: MBAR_WAIT(mb + 16, p2); p2 ^= 1; break;
            default:MBAR_WAIT(mb + 24, p3); p3 ^= 1; break;
        }

        const uint32_t Ab = shb + (uint32_t)(bi * 64 * RS) * 2u;
        const uint32_t Bb = shb + (boff + (uint32_t)(bi * 64 * RS)) * 2u;
        const int steps = KS >> 4;

        const uint32_t arow_off = (uint32_t)((wm * 32 + j + 8 * sm8) * RS + 8 * sk8) * 2u;
        const uint32_t brow_off = (uint32_t)((wn * 16 + j + 8 * sm8) * RS + 8 * sk8) * 2u;

        for (int s = 0; s < steps; ++s) {
            const uint32_t kb2 = (uint32_t)(s * 16) * 2u;
            uint32_t a0[4], a1[4], bb[4];
            ldsm_x4(a0, Ab + arow_off + kb2);
            ldsm_x4(a1, Ab + arow_off + kb2 + (uint32_t)(16 * RS) * 2u);
            ldsm_x4(bb, Bb + brow_off + kb2);
            mma16(acc[0][0], a0, bb[0], bb[2]);
            mma16(acc[0][1], a0, bb[1], bb[3]);
            mma16(acc[1][0], a1, bb[0], bb[2]);
            mma16(acc[1][1], a1, bb[1], bb[3]);
        }
        __syncthreads();                 // all warps done with stage c (and earlier)
        if (c + 3 < ns) issue(c + 3);    // reuses buf (c-1)&3, safe after barrier
    }

    // ---- epilogue ----
    float bv[2][2];
    #pragma unroll
    for (int nt = 0; nt < 2; ++nt) {
        const int cc = col0 + wn * 16 + nt * 8 + r * 2;
        bv[nt][0] = g.bias ? __ldg(g.bias + cc)     : 0.f;
        bv[nt][1] = g.bias ? __ldg(g.bias + cc + 1) : 0.f;
    }
    #pragma unroll
    for (int mt = 0; mt < 2; ++mt) {
        #pragma unroll
        for (int rh = 0; rh < 2; ++rh) {
            const int rr = row0 + wm * 32 + mt * 16 + rh * 8 + q;
            if (rr >= M) continue;
            #pragma unroll
            for (int nt = 0; nt < 2; ++nt) {
                const int cc = col0 + wn * 16 + nt * 8 + r * 2;
                const float ox = acc[mt][nt][rh * 2 + 0] + bv[nt][0];
                const float oy = acc[mt][nt][rh * 2 + 1] + bv[nt][1];
                if (omode == 2) {
                    __half2* dp = (__half2*)(g.Ch + (size_t)rr * ldc + cc);
                    *dp = __floats2half2_rn(ox, oy);
                } else {
                    float* rowp;
                    if (omode == 0) rowp = g.C + (size_t)rr * ldc;
                    else {
                        const int t = rr % S_, bbn = rr / S_;
                        rowp = g.C + (size_t)t * (B_ * D_) + (size_t)bbn * D_;
                    }
                    *(float2*)(rowp + cc) = make_float2(ox, oy);
                }
            }
        }
    }
}

// ---------------------------------------------------------------------------
// Fused prep, compact 1D grid (1840 CTAs x 256 threads), no idle blocks:
//  [0,256)     Wq   transpose 512x512
//  [256,512)   Wc   transpose 512x512
//  [512,1024)  Wout transpose 1024x512
//  [1024,1232) mem b0 transpose 400x512
//  [1232,1440) mem b1 transpose 400x512
//  [1440,1840) f32->f16 convert of input & memory
// ---------------------------------------------------------------------------
__global__ void __launch_bounds__(256) prep_kernel(
    const float* __restrict__ input, const float* __restrict__ memory,
    const float* __restrict__ Wq, const float* __restrict__ Wc,
    const float* __restrict__ Wout,
    __half* __restrict__ in_h, __half* __restrict__ mem_h,
    __half* __restrict__ WqT, __half* __restrict__ WcT,
    __half* __restrict__ WoutT, __half* __restrict__ memT)
{
    const int blk = blockIdx.x;
    const int tid = threadIdx.x;

    if (blk >= 1440) {   // conv job
        const int i = (blk - 1440) * 256 + tid;      // < 102400 = ROWS*D_/4
        float4 v = ((const float4*)input)[i];
        ((__half2*)in_h)[2 * i]     = __floats2half2_rn(v.x, v.y);
        ((__half2*)in_h)[2 * i + 1] = __floats2half2_rn(v.z, v.w);
        v = ((const float4*)memory)[i];
        ((__half2*)mem_h)[2 * i]     = __floats2half2_rn(v.x, v.y);
        ((__half2*)mem_h)[2 * i + 1] = __floats2half2_rn(v.z, v.w);
        return;
    }

    const float* I; __half* O; int R, local;
    if (blk < 256)       { I = Wq;   O = WqT;   R = 512;  local = blk; }
    else if (blk < 512)  { I = Wc;   O = WcT;   R = 512;  local = blk - 256; }
    else if (blk < 1024) { I = Wout; O = WoutT; R = 1024; local = blk - 512; }
    else if (blk < 1232) { I = memory;             O = memT;             R = 400; local = blk - 1024; }
    else                 { I = memory + 400 * 512; O = memT + 512 * 400; R = 400; local = blk - 1232; }
    const int C = 512;
    const int c0 = (local & 15) * 32;
    const int r0 = (local >> 4) * 32;

    __shared__ float t[32][33];
    const int x = tid & 31, y = tid >> 5;    // 32 x 8
    #pragma unroll
    for (int d = 0; d < 32; d += 8) {
        const int rr = r0 + y + d, cc = c0 + x;
        t[y + d][x] = (rr < R && cc < C) ? I[(size_t)rr * C + cc] : 0.f;
    }
    __syncthreads();
    #pragma unroll
    for (int d = 0; d < 32; d += 8) {
        const int orow = c0 + y + d;   // original col
        const int ocol = r0 + x;       // original row
        if (orow < C && ocol < R)
            O[(size_t)orow * R + ocol] = __float2half(t[x][y + d]);
    }
}

// ---------------------------------------------------------------------------
// FUSED scores + masked softmax.
// CTA = 2 t-rows x full s-range. grid (200, 2), 256 threads (8 warps).
// Phase 1: scores into smem (HADD2 + tanh.f16x2 + HFMA2, f32 flush).
// Phase 2: per-row masked softmax from smem; writes align f32 (d_out) + f16.
// ---------------------------------------------------------------------------
__global__ void __launch_bounds__(256) scores_softmax_kernel(
    const __half2* __restrict__ wq, const __half2* __restrict__ uh,
    const float* __restrict__ v, const int* __restrict__ lens,
    float* __restrict__ align_out, __half* __restrict__ align_h)
{
    const int b = blockIdx.y;
    const int t0 = blockIdx.x * 2;
    const int len = lens[b];

    __shared__ __half2 qsm[2][D_ / 2];
    __shared__ __half2 vsm[D_ / 2];
    __shared__ float   ssm[2][S_];
    __shared__ float   red[2][8];

    const int tid = threadIdx.x;
    for (int i = tid; i < 2 * (D_ / 2); i += 256)
        qsm[i >> 8][i & 255] = wq[((size_t)(b * S_ + t0 + (i >> 8))) * (D_ / 2) + (i & 255)];
    for (int i = tid; i < D_ / 2; i += 256)
        vsm[i] = __floats2half2_rn(v[2 * i], v[2 * i + 1]);
    __syncthreads();

    const int warp = tid >> 5, lane = tid & 31;

    // ---- Phase 1: scores for s in [0, len), 32 s per pass (4 per warp) ----
    for (int pass = 0; ; ++pass) {
        const int s0 = pass * 32 + warp * 4;
        if (pass * 32 >= len) break;            // uniform across warps
        if (s0 < len) {
            const __half2* up[4];
            #pragma unroll
            for (int j = 0; j < 4; ++j) {
                int sj = s0 + j; if (sj > S_ - 1) sj = S_ - 1;
                up[j] = uh + ((size_t)b * S_ + sj) * (D_ / 2);
            }
            float acc[2][4];
            __half2 acc2[2][4];
            const __half2 h2z = __floats2half2_rn(0.f, 0.f);
            #pragma unroll
            for (int t = 0; t < 2; ++t)
                #pragma unroll
                for (int j = 0; j < 4; ++j) { acc[t][j] = 0.f; acc2[t][j] = h2z; }

            #pragma unroll
            for (int i = 0; i < 8; ++i) {
                const int e2 = i * 32 + lane;
                const __half2 v2 = vsm[e2];
                __half2 q2[2];
                q2[0] = qsm[0][e2];
                q2[1] = qsm[1][e2];
                #pragma unroll
                for (int j = 0; j < 4; ++j) {
                    const __half2 u2 = __ldg(up[j] + e2);
                    acc2[0][j] = __hfma2(v2, tanh2_fast(__hadd2(q2[0], u2)), acc2[0][j]);
                    acc2[1][j] = __hfma2(v2, tanh2_fast(__hadd2(q2[1], u2)), acc2[1][j]);
                }
                if ((i & 3) == 3) {
                    #pragma unroll
                    for (int t = 0; t < 2; ++t)
                        #pragma unroll
                        for (int j = 0; j < 4; ++j) {
                            const float2 f = __half22float2(acc2[t][j]);
                            acc[t][j] += f.x + f.y;
                            acc2[t][j] = h2z;
                        }
                }
            }
            #pragma unroll
            for (int t = 0; t < 2; ++t)
                #pragma unroll
                for (int j = 0; j < 4; ++j) {
                    float a = acc[t][j];
                    a += __shfl_xor_sync(0xffffffffu, a, 16);
                    a += __shfl_xor_sync(0xffffffffu, a, 8);
                    a += __shfl_xor_sync(0xffffffffu, a, 4);
                    a += __shfl_xor_sync(0xffffffffu, a, 2);
                    a += __shfl_xor_sync(0xffffffffu, a, 1);
                    if (lane == t * 4 + j && s0 + j < len)
                        ssm[t][s0 + j] = a;
                }
        }
    }
    __syncthreads();

    // ---- Phase 2: masked softmax, 4 warps per row ----
    const int ti = warp >> 2;            // 0..1
    const int wr = warp & 3;             // warp within row
    const int tg = t0 + ti;              // global t
    float vals[4];
    float mx = -1e30f;
    #pragma unroll
    for (int k = 0; k < 4; ++k) {
        const int s = k * 128 + wr * 32 + lane;   // covers 0..511
        const bool ok = (s < len) && (s != tg);
        const float val = ok ? ssm[ti][s] : -1e30f;
        vals[k] = val;
        mx = fmaxf(mx, val);
    }
    #pragma unroll
    for (int o = 16; o; o >>= 1) mx = fmaxf(mx, __shfl_xor_sync(0xffffffffu, mx, o));
    if (lane == 0) red[ti][wr] = mx;
    __syncthreads();
    mx = fmaxf(fmaxf(red[ti][0], red[ti][1]), fmaxf(red[ti][2], red[ti][3]));

    float sum = 0.f;
    #pragma unroll
    for (int k = 0; k < 4; ++k) {
        const float e = (vals[k] > -1e29f) ? __expf(vals[k] - mx) : 0.f;
        vals[k] = e;
        sum += e;
    }
    #pragma unroll
    for (int o = 16; o; o >>= 1) sum += __shfl_xor_sync(0xffffffffu, sum, o);
    if (lane == 0) red[ti][4 + wr] = sum;
    __syncthreads();
    const float inv = 1.0f / (red[ti][4] + red[ti][5] + red[ti][6] + red[ti][7]);

    const size_t obase = (size_t)tg * (B_ * S_) + (size_t)b * S_;
    #pragma unroll
    for (int k = 0; k < 4; ++k) {
        const int s = k * 128 + wr * 32 + lane;
        if (s < S_) {
            const float a = vals[k] * inv;
            align_out[obase + s] = a;
            align_h[obase + s]   = __float2half(a);
        }
    }
}

// ---------------------------------------------------------------------------
extern "C" void kernel_launch(void* const* d_in, const int* in_sizes, int n_in,
                              void* d_out, int out_size)
{
    const float* input  = (const float*)d_in[0];
    const float* memory = (const float*)d_in[1];
    const int*   lens   = (const int*)d_in[2];
    const float* Wq     = (const float*)d_in[3];
    const float* bq     = (const float*)d_in[4];
    const float* Wc     = (const float*)d_in[5];
    const float* v      = (const float*)d_in[6];
    const float* Wout   = (const float*)d_in[7];
    const float* bout   = (const float*)d_in[8];
    float* out = (float*)d_out;

    __half *wq_h, *uh_h, *in_h, *mem_h, *memT_h, *WqT, *WcT, *WoutT, *ctx_h, *align_h;
    cudaGetSymbolAddress((void**)&wq_h,    g_wq_h);
    cudaGetSymbolAddress((void**)&uh_h,    g_uh_h);
    cudaGetSymbolAddress((void**)&in_h,    g_in_h);
    cudaGetSymbolAddress((void**)&mem_h,   g_mem_h);
    cudaGetSymbolAddress((void**)&memT_h,  g_memT_h);
    cudaGetSymbolAddress((void**)&WqT,     g_WqT);
    cudaGetSymbolAddress((void**)&WcT,     g_WcT);
    cudaGetSymbolAddress((void**)&WoutT,   g_WoutT);
    cudaGetSymbolAddress((void**)&ctx_h,   g_ctx_h);
    cudaGetSymbolAddress((void**)&align_h, g_align_h);

    static bool attr_set = false;
    if (!attr_set) {
        cudaFuncSetAttribute(gemm_f16, cudaFuncAttributeMaxDynamicSharedMemorySize,
                             4 * 2 * 64 * (128 + 8) * 2);   // 139264
        attr_set = true;
    }

    // ---- prep (compact fused: 4 transposes + f32->f16 conversions) ----
    prep_kernel<<<1840, 256>>>(
        input, memory, Wq, Wc, Wout, in_h, mem_h, WqT, WcT, WoutT, memT_h);

    // ---- 1) fused: z=0 -> wq_h = input@Wq + bq; z=1 -> uh_h = memory@Wc (f16 out)
    {
        GemmArgs gq{in_h,  in_h,  WqT, bq,      nullptr, wq_h};
        GemmArgs gu{mem_h, mem_h, WcT, nullptr, nullptr, uh_h};
        gemm_f16<<<dim3(8, 13, 2), 256, 4 * 2 * 64 * 136 * 2>>>(
            gq, gu, 512, 512, 512, 512, 2, 800, 512, 128);
    }
    // ---- 2) fused scores + softmax -> align (f32 in d_out, f16 copy) ----
    scores_softmax_kernel<<<dim3(200, 2), 256>>>(
        (const __half2*)wq_h, (const __half2*)uh_h, v, lens,
        out + ALIGN_OFF, align_h);
    // ---- 3) context: c[b] = align[b] @ memory[b] -> ctx_h (f16), KS=80, ns=5
    {
        GemmArgs c0{align_h,       align_h,       memT_h,             nullptr, nullptr, ctx_h};
        GemmArgs c1{align_h + S_,  align_h + S_,  memT_h + D_ * S_,   nullptr, nullptr, ctx_h + S_ * D_};
        gemm_f16<<<dim3(8, 7, 2), 256, 4 * 2 * 64 * 88 * 2>>>(
            c0, c1, 800, 400, 400, 512, 2, 400, 400, 80);
    }
    // ---- 4) attn_h = [ctx | input] @ Wout + bout -> [T,B,D] in d_out, ns=8
    {
        GemmArgs go{ctx_h, in_h, WoutT, bout, out, nullptr};
        gemm_f16<<<dim3(8, 13, 1), 256, 4 * 2 * 64 * 136 * 2>>>(
            go, go, 512, 512, 1024, 512, 1, 800, 1024, 128);
    }
}

// round 14
// speedup vs baseline: 1.2064x; 1.2064x over previous
#include <cuda_runtime.h>
#include <cuda_fp16.h>
#include <cstdint>
#include <cstddef>

// Problem constants
#define B_  2
#define S_  400
#define D_  512
#define ROWS (B_ * S_)                  // 800
#define ALIGN_OFF (S_ * B_ * D_)        // 409600

// Scratch (device globals: no allocation allowed)
__device__ __half g_wq_h[ROWS * D_];
__device__ __half g_uh_h[ROWS * D_];
__device__ __half g_in_h[ROWS * D_];
__device__ __half g_mem_h[ROWS * D_];
__device__ __half g_memT_h[B_ * D_ * S_];      // per b: [512][400]
__device__ __half g_WqT[D_ * D_];              // [n][k]
__device__ __half g_WcT[D_ * D_];
__device__ __half g_WoutT[D_ * 2 * D_];        // [512][1024]
__device__ __half g_ctx_h[ROWS * D_];
__device__ __half g_align_h[S_ * B_ * S_];     // [t][b][s]

// ---------------------------------------------------------------------------
__device__ __forceinline__ __half2 tanh2_fast(__half2 x) {
    uint32_t xi = *(uint32_t*)&x, yi;
    asm("tanh.approx.f16x2 %0, %1;" : "=r"(yi) : "r"(xi));
    return *(__half2*)&yi;
}

__device__ __forceinline__ uint32_t smem_u32(const void* p) {
    uint32_t a;
    asm("{ .reg .u64 t; cvta.to.shared.u64 t, %1; cvt.u32.u64 %0, t; }"
        : "=r"(a) : "l"(p));
    return a;
}

#define MBAR_INIT(mbar, cnt) \
    asm volatile("mbarrier.init.shared.b64 [%0], %1;" \
        :: "r"((uint32_t)(mbar)), "r"((uint32_t)(cnt)) : "memory")

#define MBAR_WAIT(mbar, parity) do { \
    uint32_t _m = (uint32_t)(mbar); uint32_t _p = (uint32_t)(parity); uint32_t _d; \
    asm volatile("{\n\t.reg .pred p;\n\t" \
        "mbarrier.try_wait.parity.acquire.cta.shared::cta.b64 p, [%1], %2;\n\t" \
        "selp.b32 %0, 1, 0, p;\n\t}" : "=r"(_d) : "r"(_m), "r"(_p) : "memory"); \
    if (!_d) { \
        asm volatile("{\n\t.reg .pred P1;\n\t" \
            "WL_%=:\n\t" \
            "mbarrier.try_wait.parity.acquire.cta.shared::cta.b64 P1, [%0], %1, 0x989680;\n\t" \
            "@P1 bra.uni WD_%=;\n\t" \
            "bra.uni WL_%=;\n\t" \
            "WD_%=:\n\t}" :: "r"(_m), "r"(_p) : "memory"); \
    } \
} while (0)

__device__ __forceinline__ void bulk_cp(uint32_t dst, const void* src,
                                        uint32_t bytes, uint32_t mbar) {
    asm volatile(
        "cp.async.bulk.shared::cluster.global.mbarrier::complete_tx::bytes "
        "[%0], [%1], %2, [%3];"
        :: "r"(dst), "l"(src), "r"(bytes), "r"(mbar) : "memory");
}

__device__ __forceinline__ void ldsm_x4(uint32_t* r, uint32_t addr) {
    asm volatile("ldmatrix.sync.aligned.m8n8.x4.shared.b16 {%0,%1,%2,%3}, [%4];"
                 : "=r"(r[0]), "=r"(r[1]), "=r"(r[2]), "=r"(r[3]) : "r"(addr));
}

__device__ __forceinline__ void mma16(float* d, const uint32_t* a,
                                      uint32_t b0, uint32_t b1) {
    asm volatile(
        "mma.sync.aligned.m16n8k16.row.col.f32.f16.f16.f32 "
        "{%0,%1,%2,%3}, {%4,%5,%6,%7}, {%8,%9}, {%0,%1,%2,%3};"
        : "+f"(d[0]), "+f"(d[1]), "+f"(d[2]), "+f"(d[3])
        : "r"(a[0]), "r"(a[1]), "r"(a[2]), "r"(a[3]), "r"(b0), "r"(b1));
}

struct GemmArgs {
    const __half* A;      // [M, KA] row-major, lda (halves)
    const __half* A2;     // [M, K-KA] row-major, lda (concat tail)
    const __half* Bt;     // [N, K] row-major, ldb  (B transposed)
    const float*  bias;   // [N] or null
    float*        C;      // f32 out (omode 0/1)
    __half*       Ch;     // f16 out (omode 2)
};

// ---------------------------------------------------------------------------
// fp16 mma.sync GEMM, 64x64 CTA tile, 256 threads (8 warps: 2M x 4N).
// K staged by KS via cp.async.bulk + mbarrier (R12 config: large stages,
// bufs in {1,2}); ldmatrix.x4 fragments.
// omode 0: C[r*ldc+c] f32; 1: [T,B,D] scatter f32; 2: Ch[r*ldc+c] f16.
// ---------------------------------------------------------------------------
__global__ void __launch_bounds__(256, 1) gemm_f16(
    GemmArgs ga0, GemmArgs ga1, int lda, int KA, int ldb, int ldc,
    int omode, int M, int K, int KS, int bufs)
{
    extern __shared__ __half sh[];
    __shared__ uint64_t mbars[2];

    const GemmArgs g = blockIdx.z ? ga1 : ga0;
    const int tid = threadIdx.x, warp = tid >> 5, lane = tid & 31;
    const int q = lane >> 2, r = lane & 3;
    const int wm = warp >> 2;                  // 0..1 : M offset 32*wm
    const int wn = warp & 3;                   // 0..3 : N offset 16*wn
    const int row0 = blockIdx.y * 64;
    const int col0 = blockIdx.x * 64;
    const int RS = KS + 8;                     // halves per smem row
    const int ns = K / KS;
    const uint32_t shb = smem_u32(sh);
    const uint32_t mb  = smem_u32(mbars);
    const uint32_t boff = (uint32_t)bufs * 64u * (uint32_t)RS;   // halves

    if (tid < 2) MBAR_INIT(mb + tid * 8, 1);
    __syncthreads();

    const int  lrow  = tid & 63;
    const bool isA   = tid < 64;
    const bool isLd  = tid < 128;
    const int  arow_g = row0 + lrow;
    const int  arow_c = (arow_g < M) ? arow_g : (M - 1);
    const uint32_t stage_bytes = (uint32_t)KS * 2u * 128u;

    auto issue = [&](int c) {
        const int bi = c & (bufs - 1);
        const uint32_t mbar = mb + (uint32_t)(c & 1) * 8u;
        if (tid == 0)
            asm volatile("mbarrier.arrive.expect_tx.shared.b64 _, [%0], %1;"
                         :: "r"(mbar), "r"(stage_bytes) : "memory");
        if (isLd) {
            const int k0 = c * KS;
            const __half* src;
            uint32_t dst;
            if (isA) {
                const __half* Ab = (k0 < KA) ? g.A : g.A2;
                const int kk = (k0 < KA) ? k0 : (k0 - KA);
                src = Ab + (size_t)arow_c * lda + kk;
                dst = shb + (uint32_t)((bi * 64 + lrow) * RS) * 2u;
            } else {
                src = g.Bt + (size_t)(col0 + lrow) * ldb + (size_t)c * KS;
                dst = shb + (boff + (uint32_t)((bi * 64 + lrow) * RS)) * 2u;
            }
            bulk_cp(dst, src, (uint32_t)KS * 2u, mbar);
        }
    };

    float acc[2][2][4];
    #pragma unroll
    for (int i = 0; i < 2; ++i)
        #pragma unroll
        for (int j2 = 0; j2 < 2; ++j2)
            #pragma unroll
            for (int k2 = 0; k2 < 4; ++k2) acc[i][j2][k2] = 0.f;

    int ph0 = 0, ph1 = 0;
    issue(0);

    const int j   = lane & 7;
    const int sm8 = (lane >> 3) & 1;
    const int sk8 = (lane >> 4) & 1;

    for (int c = 0; c < ns; ++c) {
        if (c + 1 < ns) issue(c + 1);
        if ((c & 1) == 0) { MBAR_WAIT(mb,     ph0); ph0 ^= 1; }
        else              { MBAR_WAIT(mb + 8, ph1); ph1 ^= 1; }

        const int bi = c & (bufs - 1);
        const uint32_t Ab = shb + (uint32_t)(bi * 64 * RS) * 2u;
        const uint32_t Bb = shb + (boff + (uint32_t)(bi * 64 * RS)) * 2u;
        const int steps = KS >> 4;

        const uint32_t arow_off = (uint32_t)((wm * 32 + j + 8 * sm8) * RS + 8 * sk8) * 2u;
        const uint32_t brow_off = (uint32_t)((wn * 16 + j + 8 * sm8) * RS + 8 * sk8) * 2u;

        for (int s = 0; s < steps; ++s) {
            const uint32_t kb2 = (uint32_t)(s * 16) * 2u;
            uint32_t a0[4], a1[4], bb[4];
            ldsm_x4(a0, Ab + arow_off + kb2);
            ldsm_x4(a1, Ab + arow_off + kb2 + (uint32_t)(16 * RS) * 2u);
            ldsm_x4(bb, Bb + brow_off + kb2);
            mma16(acc[0][0], a0, bb[0], bb[2]);
            mma16(acc[0][1], a0, bb[1], bb[3]);
            mma16(acc[1][0], a1, bb[0], bb[2]);
            mma16(acc[1][1], a1, bb[1], bb[3]);
        }
        __syncthreads();
    }

    // ---- epilogue ----
    float bv[2][2];
    #pragma unroll
    for (int nt = 0; nt < 2; ++nt) {
        const int cc = col0 + wn * 16 + nt * 8 + r * 2;
        bv[nt][0] = g.bias ? __ldg(g.bias + cc)     : 0.f;
        bv[nt][1] = g.bias ? __ldg(g.bias + cc + 1) : 0.f;
    }
    #pragma unroll
    for (int mt = 0; mt < 2; ++mt) {
        #pragma unroll
        for (int rh = 0; rh < 2; ++rh) {
            const int rr = row0 + wm * 32 + mt * 16 + rh * 8 + q;
            if (rr >= M) continue;
            #pragma unroll
            for (int nt = 0; nt < 2; ++nt) {
                const int cc = col0 + wn * 16 + nt * 8 + r * 2;
                const float ox = acc[mt][nt][rh * 2 + 0] + bv[nt][0];
                const float oy = acc[mt][nt][rh * 2 + 1] + bv[nt][1];
                if (omode == 2) {
                    __half2* dp = (__half2*)(g.Ch + (size_t)rr * ldc + cc);
                    *dp = __floats2half2_rn(ox, oy);
                } else {
                    float* rowp;
                    if (omode == 0) rowp = g.C + (size_t)rr * ldc;
                    else {
                        const int t = rr % S_, bbn = rr / S_;
                        rowp = g.C + (size_t)t * (B_ * D_) + (size_t)bbn * D_;
                    }
                    *(float2*)(rowp + cc) = make_float2(ox, oy);
                }
            }
        }
    }
}

// ---------------------------------------------------------------------------
// Fused prep, compact 1D grid (1840 CTAs x 256 threads), no idle blocks:
//  [0,256)     Wq   transpose 512x512
//  [256,512)   Wc   transpose 512x512
//  [512,1024)  Wout transpose 1024x512
//  [1024,1232) mem b0 transpose 400x512
//  [1232,1440) mem b1 transpose 400x512
//  [1440,1840) f32->f16 convert of input & memory
// ---------------------------------------------------------------------------
__global__ void __launch_bounds__(256) prep_kernel(
    const float* __restrict__ input, const float* __restrict__ memory,
    const float* __restrict__ Wq, const float* __restrict__ Wc,
    const float* __restrict__ Wout,
    __half* __restrict__ in_h, __half* __restrict__ mem_h,
    __half* __restrict__ WqT, __half* __restrict__ WcT,
    __half* __restrict__ WoutT, __half* __restrict__ memT)
{
    const int blk = blockIdx.x;
    const int tid = threadIdx.x;

    if (blk >= 1440) {   // conv job
        const int i = (blk - 1440) * 256 + tid;      // < 102400 = ROWS*D_/4
        float4 v = ((const float4*)input)[i];
        ((__half2*)in_h)[2 * i]     = __floats2half2_rn(v.x, v.y);
        ((__half2*)in_h)[2 * i + 1] = __floats2half2_rn(v.z, v.w);
        v = ((const float4*)memory)[i];
        ((__half2*)mem_h)[2 * i]     = __floats2half2_rn(v.x, v.y);
        ((__half2*)mem_h)[2 * i + 1] = __floats2half2_rn(v.z, v.w);
        return;
    }

    const float* I; __half* O; int R, local;
    if (blk < 256)       { I = Wq;   O = WqT;   R = 512;  local = blk; }
    else if (blk < 512)  { I = Wc;   O = WcT;   R = 512;  local = blk - 256; }
    else if (blk < 1024) { I = Wout; O = WoutT; R = 1024; local = blk - 512; }
    else if (blk < 1232) { I = memory;             O = memT;             R = 400; local = blk - 1024; }
    else                 { I = memory + 400 * 512; O = memT + 512 * 400; R = 400; local = blk - 1232; }
    const int C = 512;
    const int c0 = (local & 15) * 32;
    const int r0 = (local >> 4) * 32;

    __shared__ float t[32][33];
    const int x = tid & 31, y = tid >> 5;    // 32 x 8
    #pragma unroll
    for (int d = 0; d < 32; d += 8) {
        const int rr = r0 + y + d, cc = c0 + x;
        t[y + d][x] = (rr < R && cc < C) ? I[(size_t)rr * C + cc] : 0.f;
    }
    __syncthreads();
    #pragma unroll
    for (int d = 0; d < 32; d += 8) {
        const int orow = c0 + y + d;   // original col
        const int ocol = r0 + x;       // original row
        if (orow < C && ocol < R)
            O[(size_t)orow * R + ocol] = __float2half(t[x][y + d]);
    }
}

// ---------------------------------------------------------------------------
// FUSED scores + masked softmax.
// CTA = 2 t-rows x full s-range. grid (200, 2), 256 threads (8 warps).
// Phase 1: scores into smem (HADD2 + tanh.f16x2 + HFMA2, f32 flush).
// Phase 2: per-row masked softmax from smem; writes align f32 (d_out) + f16.
// ---------------------------------------------------------------------------
__global__ void __launch_bounds__(256) scores_softmax_kernel(
    const __half2* __restrict__ wq, const __half2* __restrict__ uh,
    const float* __restrict__ v, const int* __restrict__ lens,
    float* __restrict__ align_out, __half* __restrict__ align_h)
{
    const int b = blockIdx.y;
    const int t0 = blockIdx.x * 2;
    const int len = lens[b];

    __shared__ __half2 qsm[2][D_ / 2];
    __shared__ __half2 vsm[D_ / 2];
    __shared__ float   ssm[2][S_];
    __shared__ float   red[2][8];

    const int tid = threadIdx.x;
    for (int i = tid; i < 2 * (D_ / 2); i += 256)
        qsm[i >> 8][i & 255] = wq[((size_t)(b * S_ + t0 + (i >> 8))) * (D_ / 2) + (i & 255)];
    for (int i = tid; i < D_ / 2; i += 256)
        vsm[i] = __floats2half2_rn(v[2 * i], v[2 * i + 1]);
    __syncthreads();

    const int warp = tid >> 5, lane = tid & 31;

    // ---- Phase 1: scores for s in [0, len), 32 s per pass (4 per warp) ----
    for (int pass = 0; ; ++pass) {
        const int s0 = pass * 32 + warp * 4;
        if (pass * 32 >= len) break;            // uniform across warps
        if (s0 < len) {
            const __half2* up[4];
            #pragma unroll
            for (int j = 0; j < 4; ++j) {
                int sj = s0 + j; if (sj > S_ - 1) sj = S_ - 1;
                up[j] = uh + ((size_t)b * S_ + sj) * (D_ / 2);
            }
            float acc[2][4];
            __half2 acc2[2][4];
            const __half2 h2z = __floats2half2_rn(0.f, 0.f);
            #pragma unroll
            for (int t = 0; t < 2; ++t)
                #pragma unroll
                for (int j = 0; j < 4; ++j) { acc[t][j] = 0.f; acc2[t][j] = h2z; }

            #pragma unroll
            for (int i = 0; i < 8; ++i) {
                const int e2 = i * 32 + lane;
                const __half2 v2 = vsm[e2];
                __half2 q2[2];
                q2[0] = qsm[0][e2];
                q2[1] = qsm[1][e2];
                #pragma unroll
                for (int j = 0; j < 4; ++j) {
                    const __half2 u2 = __ldg(up[j] + e2);
                    acc2[0][j] = __hfma2(v2, tanh2_fast(__hadd2(q2[0], u2)), acc2[0][j]);
                    acc2[1][j] = __hfma2(v2, tanh2_fast(__hadd2(q2[1], u2)), acc2[1][j]);
                }
                if ((i & 3) == 3) {
                    #pragma unroll
                    for (int t = 0; t < 2; ++t)
                        #pragma unroll
                        for (int j = 0; j < 4; ++j) {
                            const float2 f = __half22float2(acc2[t][j]);
                            acc[t][j] += f.x + f.y;
                            acc2[t][j] = h2z;
                        }
                }
            }
            #pragma unroll
            for (int t = 0; t < 2; ++t)
                #pragma unroll
                for (int j = 0; j < 4; ++j) {
                    float a = acc[t][j];
                    a += __shfl_xor_sync(0xffffffffu, a, 16);
                    a += __shfl_xor_sync(0xffffffffu, a, 8);
                    a += __shfl_xor_sync(0xffffffffu, a, 4);
                    a += __shfl_xor_sync(0xffffffffu, a, 2);
                    a += __shfl_xor_sync(0xffffffffu, a, 1);
                    if (lane == t * 4 + j && s0 + j < len)
                        ssm[t][s0 + j] = a;
                }
        }
    }
    __syncthreads();

    // ---- Phase 2: masked softmax, 4 warps per row ----
    const int ti = warp >> 2;            // 0..1
    const int wr = warp & 3;             // warp within row
    const int tg = t0 + ti;              // global t
    float vals[4];
    float mx = -1e30f;
    #pragma unroll
    for (int k = 0; k < 4; ++k) {
        const int s = k * 128 + wr * 32 + lane;   // covers 0..511
        const bool ok = (s < len) && (s != tg);
        const float val = ok ? ssm[ti][s] : -1e30f;
        vals[k] = val;
        mx = fmaxf(mx, val);
    }
    #pragma unroll
    for (int o = 16; o; o >>= 1) mx = fmaxf(mx, __shfl_xor_sync(0xffffffffu, mx, o));
    if (lane == 0) red[ti][wr] = mx;
    __syncthreads();
    mx = fmaxf(fmaxf(red[ti][0], red[ti][1]), fmaxf(red[ti][2], red[ti][3]));

    float sum = 0.f;
    #pragma unroll
    for (int k = 0; k < 4; ++k) {
        const float e = (vals[k] > -1e29f) ? __expf(vals[k] - mx) : 0.f;
        vals[k] = e;
        sum += e;
    }
    #pragma unroll
    for (int o = 16; o; o >>= 1) sum += __shfl_xor_sync(0xffffffffu, sum, o);
    if (lane == 0) red[ti][4 + wr] = sum;
    __syncthreads();
    const float inv = 1.0f / (red[ti][4] + red[ti][5] + red[ti][6] + red[ti][7]);

    const size_t obase = (size_t)tg * (B_ * S_) + (size_t)b * S_;
    #pragma unroll
    for (int k = 0; k < 4; ++k) {
        const int s = k * 128 + wr * 32 + lane;
        if (s < S_) {
            const float a = vals[k] * inv;
            align_out[obase + s] = a;
            align_h[obase + s]   = __float2half(a);
        }
    }
}

// ---------------------------------------------------------------------------
extern "C" void kernel_launch(void* const* d_in, const int* in_sizes, int n_in,
                              void* d_out, int out_size)
{
    const float* input  = (const float*)d_in[0];
    const float* memory = (const float*)d_in[1];
    const int*   lens   = (const int*)d_in[2];
    const float* Wq     = (const float*)d_in[3];
    const float* bq     = (const float*)d_in[4];
    const float* Wc     = (const float*)d_in[5];
    const float* v      = (const float*)d_in[6];
    const float* Wout   = (const float*)d_in[7];
    const float* bout   = (const float*)d_in[8];
    float* out = (float*)d_out;

    __half *wq_h, *uh_h, *in_h, *mem_h, *memT_h, *WqT, *WcT, *WoutT, *ctx_h, *align_h;
    cudaGetSymbolAddress((void**)&wq_h,    g_wq_h);
    cudaGetSymbolAddress((void**)&uh_h,    g_uh_h);
    cudaGetSymbolAddress((void**)&in_h,    g_in_h);
    cudaGetSymbolAddress((void**)&mem_h,   g_mem_h);
    cudaGetSymbolAddress((void**)&memT_h,  g_memT_h);
    cudaGetSymbolAddress((void**)&WqT,     g_WqT);
    cudaGetSymbolAddress((void**)&WcT,     g_WcT);
    cudaGetSymbolAddress((void**)&WoutT,   g_WoutT);
    cudaGetSymbolAddress((void**)&ctx_h,   g_ctx_h);
    cudaGetSymbolAddress((void**)&align_h, g_align_h);

    static bool attr_set = false;
    if (!attr_set) {
        cudaFuncSetAttribute(gemm_f16, cudaFuncAttributeMaxDynamicSharedMemorySize,
                             2 * 2 * 64 * (256 + 8) * 2);   // 135168
        attr_set = true;
    }

    // ---- prep (compact fused: 4 transposes + f32->f16 conversions) ----
    prep_kernel<<<1840, 256>>>(
        input, memory, Wq, Wc, Wout, in_h, mem_h, WqT, WcT, WoutT, memT_h);

    // ---- 1) fused: z=0 -> wq_h = input@Wq + bq; z=1 -> uh_h = memory@Wc (f16 out)
    {
        GemmArgs gq{in_h,  in_h,  WqT, bq,      nullptr, wq_h};
        GemmArgs gu{mem_h, mem_h, WcT, nullptr, nullptr, uh_h};
        gemm_f16<<<dim3(8, 13, 2), 256, 2 * 2 * 64 * 264 * 2>>>(
            gq, gu, 512, 512, 512, 512, 2, 800, 512, 256, 2);
    }
    // ---- 2) fused scores + softmax -> align (f32 in d_out, f16 copy) ----
    scores_softmax_kernel<<<dim3(200, 2), 256>>>(
        (const __half2*)wq_h, (const __half2*)uh_h, v, lens,
        out + ALIGN_OFF, align_h);
    // ---- 3) context: c[b] = align[b] @ memory[b] -> ctx_h (f16) ----
    {
        GemmArgs c0{align_h,       align_h,       memT_h,             nullptr, nullptr, ctx_h};
        GemmArgs c1{align_h + S_,  align_h + S_,  memT_h + D_ * S_,   nullptr, nullptr, ctx_h + S_ * D_};
        gemm_f16<<<dim3(8, 7, 2), 256, 1 * 2 * 64 * 408 * 2>>>(
            c0, c1, 800, 400, 400, 512, 2, 400, 400, 400, 1);
    }
    // ---- 4) attn_h = [ctx | input] @ Wout + bout -> [T,B,D] in d_out ----
    {
        GemmArgs go{ctx_h, in_h, WoutT, bout, out, nullptr};
        gemm_f16<<<dim3(8, 13, 1), 256, 2 * 2 * 64 * 264 * 2>>>(
            go, go, 512, 512, 1024, 512, 1, 800, 1024, 256, 2);
    }
}